// round 7
// baseline (speedup 1.0000x reference)
#include <cuda_runtime.h>

// MakeCutouts: 32 cutouts of x[8,3,512,512] fp32, adaptive-avg-pool (torch
// bins) to 224x224. Output [256, 3, 224, 224] fp32.
//
// Block = (cut, plane, 8-row y-group), 256 threads.
// Phase 1 (streaming): each thread owns a float2 column pair. Stream the
//   block's input-row range [k0, kend) ONCE, keeping running column sums;
//   at each y-bin boundary emit bin = cum - base (base snapshot handles the
//   <=1-row overlap between consecutive ceil-bins). Next row prefetched.
// Phase 2: 224 threads x 8 rows, each sums nx (<=4) shared floats.
// All bin-boundary branches are uniform (sz uniform per block).

#define OUTS   224
#define BATCH  8
#define CHAN   3
#define HW     512
#define CUTN   32
#define NPLANE (BATCH * CHAN)   // 24
#define YG     8                // output rows per block
#define NYG    (OUTS / YG)      // 28
#define CSTRIDE 516

__device__ __forceinline__ float inv_small(int n) {
    return n == 1 ? 1.0f : (n == 2 ? 0.5f : (n == 3 ? (1.0f / 3.0f) : 0.25f));
}

__global__ __launch_bounds__(256)
void makecutouts_v6(const float* __restrict__ x,
                    const int* __restrict__ sizes,
                    const int* __restrict__ offy,
                    const int* __restrict__ offx,
                    float* __restrict__ out)
{
    __shared__ float buf[YG][CSTRIDE];   // 16,512 B
    __shared__ float invy_sh[YG];

    const int tid = threadIdx.x;
    int bid = blockIdx.x;
    const int yg    = bid % NYG;  bid /= NYG;
    const int plane = bid % NPLANE;
    const int cut   = bid / NPLANE;

    const int sz = __ldg(sizes + cut);
    const int oy = __ldg(offy + cut);
    const int ox = __ldg(offx + cut);

    const int ox_al = ox & ~1;           // float2 alignment
    const int shift = ox - ox_al;        // 0..1
    const int span  = shift + sz;        // <= 512 (sz=512 forces ox=0)
    const int y0 = yg * YG;

    if (tid < YG) {
        const int yy = y0 + tid;
        const int ny = ((yy + 1) * sz + (OUTS - 1)) / OUTS - (yy * sz) / OUTS;
        invy_sh[tid] = inv_small(ny);
    }

    // ---- Phase 1: stream rows [k0, kend) once ----
    const int k0   = (y0 * sz) / OUTS;                          // sy of bin 0
    const int kend = ((y0 + YG) * sz + (OUTS - 1)) / OUTS;      // ey of bin 7

    const int w = tid * 2;
    const bool full = (w + 1 < span);
    const bool has1 = (w < span);

    const float* rp = x + (long long)plane * (HW * HW)
                        + (long long)(oy + k0) * HW + ox_al + w;

    float c0 = 0.0f, c1 = 0.0f;   // running column sums
    float b0 = 0.0f, b1 = 0.0f;   // snapshot at current bin start
    int bin = 0;
    int eyc = ((y0 + 1) * sz + (OUTS - 1)) / OUTS;  // ey of bin 0

    // prefetch first row
    float a0 = 0.0f, a1 = 0.0f;
    if (full)      { float2 v = *(const float2*)rp; a0 = v.x; a1 = v.y; }
    else if (has1) { a0 = __ldg(rp); }

    #pragma unroll 1
    for (int k = k0; k < kend; k++) {
        // prefetch next row (guarded: row oy+kend may be out of the tensor)
        float n0 = 0.0f, n1 = 0.0f;
        if (k + 1 < kend) {
            const float* rq = rp + HW;
            if (full)      { float2 v = *(const float2*)rq; n0 = v.x; n1 = v.y; }
            else if (has1) { n0 = __ldg(rq); }
        }

        c0 += a0; c1 += a1;
        rp += HW;

        if (k + 1 == eyc) {          // uniform branch: bin complete
            if (full) {
                *(float2*)&buf[bin][w] = make_float2(c0 - b0, c1 - b1);
            } else if (has1) {
                buf[bin][w] = c0 - b0;
            }
            bin++;
            if (bin < YG) {
                const int yy  = y0 + bin;
                const int syn = (yy * sz) / OUTS;              // k or k+1
                const int eyn = ((yy + 1) * sz + (OUTS - 1)) / OUTS;
                if (syn == k) { b0 = c0 - a0; b1 = c1 - a1; }  // 1-row overlap
                else          { b0 = c0;      b1 = c1;      }
                eyc = eyn;
            }
        }
        a0 = n0; a1 = n1;
    }

    __syncthreads();

    // ---- Phase 2: 224 threads x 8 rows ----
    if (tid < OUTS) {
        const int sx = (tid * sz) / OUTS;
        const int ex = ((tid + 1) * sz + (OUTS - 1)) / OUTS;
        const int nx = ex - sx;              // 1..4
        const float invx = inv_small(nx);
        const int off = shift + sx;

        long long oidx =
            ((long long)(cut * NPLANE + plane) * OUTS + y0) * OUTS + tid;

        #pragma unroll
        for (int i = 0; i < YG; i++) {
            const float* p = &buf[i][off];
            float s = p[0];
            if (nx > 1) s += p[1];
            if (nx > 2) s += p[2];
            if (nx > 3) s += p[3];

            out[oidx] = s * (invx * invy_sh[i]);
            oidx += OUTS;
        }
    }
}

extern "C" void kernel_launch(void* const* d_in, const int* in_sizes, int n_in,
                              void* d_out, int out_size)
{
    const float* x     = (const float*)d_in[0];
    const int*   sizes = (const int*)d_in[1];
    const int*   oy    = (const int*)d_in[2];
    const int*   ox    = (const int*)d_in[3];
    float* out = (float*)d_out;

    const int blocks = CUTN * NPLANE * NYG;   // 21504
    makecutouts_v6<<<blocks, 256>>>(x, sizes, oy, ox, out);
}

// round 8
// speedup vs baseline: 1.4391x; 1.4391x over previous
#include <cuda_runtime.h>

// MakeCutouts: 32 cutouts of x[8,3,512,512] fp32, adaptive-avg-pool (torch
// bins) to 224x224. Output [256, 3, 224, 224] fp32.
//
// Block = (cut, plane, 8-row y-group), 256 threads, smem 16.5KB (full occ).
//   Phase 1: half 0 (threads 0-127) computes bins 0-3, half 1 bins 4-7,
//            consecutive bins per half; the <=1-row overlap between
//            consecutive bins is carried in registers (no re-load).
//            float4 loads aligned-down from ox.
//   Phase 2: 224 threads x 8 rows, each sums nx (<=4) shared floats.
// Bins span <= 4 input pixels (sz/224 < 3).

#define OUTS   224
#define BATCH  8
#define CHAN   3
#define HW     512
#define CUTN   32
#define NPLANE (BATCH * CHAN)   // 24
#define YG     8                // output rows per block
#define NYG    (OUTS / YG)      // 28
#define BPH    4                // bins per half
#define CSTRIDE 516

__device__ __forceinline__ float inv_small(int n) {
    return n == 1 ? 1.0f : (n == 2 ? 0.5f : (n == 3 ? (1.0f / 3.0f) : 0.25f));
}

__device__ __forceinline__ void f4add(float4& a, const float4 b) {
    a.x += b.x; a.y += b.y; a.z += b.z; a.w += b.w;
}

__global__ __launch_bounds__(256)
void makecutouts_v7(const float* __restrict__ x,
                    const int* __restrict__ sizes,
                    const int* __restrict__ offy,
                    const int* __restrict__ offx,
                    float* __restrict__ out)
{
    __shared__ float buf[YG][CSTRIDE];   // 16,512 B
    __shared__ float invy_sh[YG];

    const int tid = threadIdx.x;
    int bid = blockIdx.x;
    const int yg    = bid % NYG;  bid /= NYG;
    const int plane = bid % NPLANE;
    const int cut   = bid / NPLANE;

    const int sz = __ldg(sizes + cut);
    const int oy = __ldg(offy + cut);
    const int ox = __ldg(offx + cut);

    const int ox_al = ox & ~3;
    const int shift = ox - ox_al;        // 0..3
    const int span  = shift + sz;        // <= 515
    const int y0 = yg * YG;

    if (tid < YG) {
        const int yy = y0 + tid;
        const int ny = ((yy + 1) * sz + (OUTS - 1)) / OUTS - (yy * sz) / OUTS;
        invy_sh[tid] = inv_small(ny);
    }

    const float* pbase = x + (long long)plane * (HW * HW) + ox_al
                           + (long long)oy * HW;

    // ---- Phase 1: consecutive bins per half, carry overlap row ----
    const int lane = tid & 127;
    const int half = tid >> 7;
    const int rem  = span - lane * 4;
    const int col4 = lane * 4;
    const int yb   = y0 + half * BPH;

    if (rem >= 4) {
        float4 last;                 // value of row (pe-1)
        int pe = -1000;              // prev bin's ey

        #pragma unroll
        for (int j = 0; j < BPH; j++) {
            const int y  = yb + j;
            const int sy = (y * sz) / OUTS;
            const int ey = ((y + 1) * sz + (OUTS - 1)) / OUTS;
            const int nrows = ey - sy;            // 1..4

            const float* rp = pbase + (long long)sy * HW + col4;

            float4 acc, l;
            if (sy == pe - 1) {                   // overlap: reuse carried row
                acc = last; l = last;
            } else {
                l = __ldg((const float4*)rp);
                acc = l;
            }
            if (nrows > 1) { l = __ldg((const float4*)(rp + HW));     f4add(acc, l); }
            if (nrows > 2) { l = __ldg((const float4*)(rp + 2 * HW)); f4add(acc, l); }
            if (nrows > 3) { l = __ldg((const float4*)(rp + 3 * HW)); f4add(acc, l); }

            *(float4*)&buf[half * BPH + j][col4] = acc;
            last = l;
            pe = ey;
        }
    } else if (rem > 0) {
        // partial tail lane: 1..3 scalar columns (v5-style, tiny fraction)
        #pragma unroll
        for (int j = 0; j < BPH; j++) {
            const int y  = yb + j;
            const int sy = (y * sz) / OUTS;
            const int nrows = ((y + 1) * sz + (OUTS - 1)) / OUTS - sy;
            const float* rp = pbase + (long long)sy * HW + col4;
            #pragma unroll
            for (int k = 0; k < 3; k++) {
                if (k < rem) {
                    float s = __ldg(rp + k);
                    if (nrows > 1) s += __ldg(rp + k + HW);
                    if (nrows > 2) s += __ldg(rp + k + 2 * HW);
                    if (nrows > 3) s += __ldg(rp + k + 3 * HW);
                    buf[half * BPH + j][col4 + k] = s;
                }
            }
        }
    }
    // columns 512..514 (only when span > 512): lane 126 of half 0 handles
    if (span > 512 && tid == 126) {
        #pragma unroll
        for (int j = 0; j < YG; j++) {
            const int y  = y0 + j;
            const int sy = (y * sz) / OUTS;
            const int nrows = ((y + 1) * sz + (OUTS - 1)) / OUTS - sy;
            #pragma unroll
            for (int c = 512; c < 515; c++) {
                if (c < span) {
                    const float* q = pbase + (long long)sy * HW + c;
                    float s = __ldg(q);
                    if (nrows > 1) s += __ldg(q + HW);
                    if (nrows > 2) s += __ldg(q + 2 * HW);
                    if (nrows > 3) s += __ldg(q + 3 * HW);
                    buf[j][c] = s;
                }
            }
        }
    }

    __syncthreads();

    // ---- Phase 2: 224 threads x 8 rows, no barriers ----
    if (tid < OUTS) {
        const int sx = (tid * sz) / OUTS;
        const int ex = ((tid + 1) * sz + (OUTS - 1)) / OUTS;
        const int nx = ex - sx;              // 1..4
        const float invx = inv_small(nx);
        const int off = shift + sx;

        long long oidx =
            ((long long)(cut * NPLANE + plane) * OUTS + y0) * OUTS + tid;

        #pragma unroll
        for (int i = 0; i < YG; i++) {
            const float* p = &buf[i][off];
            float s = p[0];
            if (nx > 1) s += p[1];
            if (nx > 2) s += p[2];
            if (nx > 3) s += p[3];

            out[oidx] = s * (invx * invy_sh[i]);
            oidx += OUTS;
        }
    }
}

extern "C" void kernel_launch(void* const* d_in, const int* in_sizes, int n_in,
                              void* d_out, int out_size)
{
    const float* x     = (const float*)d_in[0];
    const int*   sizes = (const int*)d_in[1];
    const int*   oy    = (const int*)d_in[2];
    const int*   ox    = (const int*)d_in[3];
    float* out = (float*)d_out;

    const int blocks = CUTN * NPLANE * NYG;   // 21504
    makecutouts_v7<<<blocks, 256>>>(x, sizes, oy, ox, out);
}